// round 2
// baseline (speedup 1.0000x reference)
#include <cuda_runtime.h>
#include <cuda_bf16.h>

// Problem constants (fixed by the dataset)
#define NUM_REL_MAX   20000
#define NUM_EDGES_MAX 640000
#define DIM           128
#define NUM_HEAD      8
#define DIM_HID       16
#define NEG_SLOPE     0.2f

// Scratch (device globals -- no allocation allowed)
__device__ float g_A[NUM_REL_MAX * DIM];       // emb @ W1^T + attn_bias
__device__ float g_B[NUM_REL_MAX * DIM];       // emb @ W2^T
__device__ float g_MSG[NUM_REL_MAX * DIM];     // emb @ aggr^T + aggr_bias
__device__ float g_attn[NUM_EDGES_MAX * NUM_HEAD];   // per-edge exp(attn_raw)
__device__ float g_segsum[NUM_REL_MAX * NUM_HEAD];   // per (rel, head) sum
__device__ int   g_is64;                             // triplet dtype flag

__device__ __forceinline__ float leaky(float x) {
    return x >= 0.0f ? x : NEG_SLOPE * x;
}

// ---------------------------------------------------------------------------
// Detect triplet dtype: int64 values < 2^31 -> all odd 32-bit words are 0.
// int32 triplets -> odd words are tail/head indices, essentially never all 0.
// ---------------------------------------------------------------------------
__global__ void detect_kernel(const unsigned int* __restrict__ trip_w, int nwords) {
    // single block, 128 threads; check odd words in the first 512 words
    __shared__ int any_nonzero;
    if (threadIdx.x == 0) any_nonzero = 0;
    __syncthreads();
    int i = 1 + 2 * threadIdx.x;   // odd words
    if (i < nwords && i < 512) {
        if (trip_w[i] != 0u) atomicOr(&any_nonzero, 1);
    }
    __syncthreads();
    if (threadIdx.x == 0) g_is64 = any_nonzero ? 0 : 1;
}

// ---------------------------------------------------------------------------
// Zero init: out [M*128] and g_segsum [M*8]
// ---------------------------------------------------------------------------
__global__ void zero_kernel(float* __restrict__ out, int M) {
    int n_out = M * DIM;
    int n_seg = M * NUM_HEAD;
    int total = n_out + n_seg;
    for (int i = blockIdx.x * blockDim.x + threadIdx.x; i < total;
         i += gridDim.x * blockDim.x) {
        if (i < n_out) out[i] = 0.0f;
        else g_segsum[i - n_out] = 0.0f;
    }
}

// ---------------------------------------------------------------------------
// Fused SGEMM: P[M, 384] = emb[M,128] @ Wc[384,128]^T  (+ biases)
//   cols [0,128)   -> g_A   (weights attn_w[c][0:128],   bias attn_b[c])
//   cols [128,256) -> g_B   (weights attn_w[c-128][128:256])
//   cols [256,384) -> g_MSG (weights aggr_w[c-256],      bias aggr_b)
// BM=BN=64, full K=128 in smem, 256 threads, 4x4 microtile.
// ---------------------------------------------------------------------------
#define BM 64
#define BN 64

__global__ __launch_bounds__(256) void gemm_kernel(
    const float* __restrict__ emb,
    const float* __restrict__ attn_w,   // [128, 256]
    const float* __restrict__ attn_b,   // [128]
    const float* __restrict__ aggr_w,   // [128, 128]
    const float* __restrict__ aggr_b,   // [128]
    int M)
{
    __shared__ float As[DIM][BM];   // transposed: As[k][row]
    __shared__ float Ws[DIM][BN];   // transposed: Ws[k][col]

    int tid = threadIdx.x;
    int m0 = blockIdx.x * BM;
    int c0 = blockIdx.y * BN;       // global output col base (0..320)

    #pragma unroll
    for (int i = 0; i < 8; i++) {
        int linear = tid + i * 256;       // 0..2047
        int row = linear & 63;
        int c4  = linear >> 6;            // 0..31
        float4 v = make_float4(0.f, 0.f, 0.f, 0.f);
        int gr = m0 + row;
        if (gr < M) v = *(const float4*)(emb + (long)gr * DIM + c4 * 4);
        As[c4 * 4 + 0][row] = v.x;
        As[c4 * 4 + 1][row] = v.y;
        As[c4 * 4 + 2][row] = v.z;
        As[c4 * 4 + 3][row] = v.w;
    }
    #pragma unroll
    for (int i = 0; i < 8; i++) {
        int linear = tid + i * 256;
        int col = linear & 63;
        int c4  = linear >> 6;
        int gc = c0 + col;
        const float* wrow;
        if (gc < 128)      wrow = attn_w + (long)gc * 256;
        else if (gc < 256) wrow = attn_w + (long)(gc - 128) * 256 + 128;
        else               wrow = aggr_w + (long)(gc - 256) * 128;
        float4 v = *(const float4*)(wrow + c4 * 4);
        Ws[c4 * 4 + 0][col] = v.x;
        Ws[c4 * 4 + 1][col] = v.y;
        Ws[c4 * 4 + 2][col] = v.z;
        Ws[c4 * 4 + 3][col] = v.w;
    }
    __syncthreads();

    int ty = tid >> 4;   // 0..15 -> row group
    int tx = tid & 15;   // 0..15 -> col group
    float acc[4][4] = {};

    #pragma unroll 16
    for (int k = 0; k < DIM; k++) {
        float4 a = *(const float4*)&As[k][ty * 4];
        float4 w = *(const float4*)&Ws[k][tx * 4];
        float av[4] = {a.x, a.y, a.z, a.w};
        float wv[4] = {w.x, w.y, w.z, w.w};
        #pragma unroll
        for (int i = 0; i < 4; i++)
            #pragma unroll
            for (int j = 0; j < 4; j++)
                acc[i][j] += av[i] * wv[j];
    }

    #pragma unroll
    for (int i = 0; i < 4; i++) {
        int gr = m0 + ty * 4 + i;
        if (gr >= M) continue;
        #pragma unroll
        for (int j = 0; j < 4; j++) {
            int gc = c0 + tx * 4 + j;
            float val = acc[i][j];
            if (gc < 128) {
                g_A[(long)gr * DIM + gc] = val + attn_b[gc];
            } else if (gc < 256) {
                g_B[(long)gr * DIM + (gc - 128)] = val;
            } else {
                g_MSG[(long)gr * DIM + (gc - 256)] = val + aggr_b[gc - 256];
            }
        }
    }
}

// ---------------------------------------------------------------------------
// Triplet fetch handling either int32 or int64 storage.
// ---------------------------------------------------------------------------
__device__ __forceinline__ void load_triplet(const void* trip, int is64, long e,
                                             int& h, int& t, int& b) {
    if (is64) {
        const long long* p = (const long long*)trip;
        h = (int)p[e * 3 + 0];
        t = (int)p[e * 3 + 1];
        b = (int)p[e * 3 + 2];
    } else {
        const int* p = (const int*)trip;
        h = p[e * 3 + 0];
        t = p[e * 3 + 1];
        b = p[e * 3 + 2];
    }
}

// ---------------------------------------------------------------------------
// Edge pass 1: one warp per edge.
//   s = leaky(A[h] + B[t])  (bias folded in A)
//   attn_raw[k] = dot over head-k dims with attn_vec + leaky(attn_bin[b][k])
//   attn_val = exp(attn_raw)  (max-subtraction skipped: cancels in beta)
// ---------------------------------------------------------------------------
__global__ __launch_bounds__(256) void edge_attn_kernel(
    const void* __restrict__ trip,
    const float* __restrict__ attn_bin,   // [10, 8]
    const float* __restrict__ attn_vec,   // [128]
    int E)
{
    long warp = (long)(blockIdx.x * (blockDim.x >> 5)) + (threadIdx.x >> 5);
    int lane = threadIdx.x & 31;
    if (warp >= E) return;

    int is64 = g_is64;
    int h, t, b;
    load_triplet(trip, is64, warp, h, t, b);

    float4 a  = *(const float4*)(g_A + (long)h * DIM + lane * 4);
    float4 bb = *(const float4*)(g_B + (long)t * DIM + lane * 4);
    float4 v  = *(const float4*)(attn_vec + lane * 4);

    float s = leaky(a.x + bb.x) * v.x
            + leaky(a.y + bb.y) * v.y
            + leaky(a.z + bb.z) * v.z
            + leaky(a.w + bb.w) * v.w;
    // reduce over the 4 lanes covering one head (16 dims)
    s += __shfl_xor_sync(0xFFFFFFFFu, s, 1);
    s += __shfl_xor_sync(0xFFFFFFFFu, s, 2);

    if ((lane & 3) == 0) {
        int k = lane >> 2;                       // head index 0..7
        float ab = __ldg(attn_bin + b * NUM_HEAD + k);
        float val = __expf(s + leaky(ab));
        g_attn[warp * NUM_HEAD + k] = val;
        atomicAdd(&g_segsum[(long)h * NUM_HEAD + k], val);
    }
}

// ---------------------------------------------------------------------------
// Edge pass 2: one warp per edge. beta = val / (seg_sum + 1e-16);
// out[h] += beta * MSG[t]
// ---------------------------------------------------------------------------
__global__ __launch_bounds__(256) void edge_scatter_kernel(
    const void* __restrict__ trip,
    float* __restrict__ out,
    int E)
{
    long warp = (long)(blockIdx.x * (blockDim.x >> 5)) + (threadIdx.x >> 5);
    int lane = threadIdx.x & 31;
    if (warp >= E) return;

    int is64 = g_is64;
    int h, t, b;
    load_triplet(trip, is64, warp, h, t, b);

    int k = lane >> 2;
    float val  = g_attn[warp * NUM_HEAD + k];
    float ssum = g_segsum[(long)h * NUM_HEAD + k];
    float beta = val / (ssum + 1e-16f);

    float4 m = *(const float4*)(g_MSG + (long)t * DIM + lane * 4);
    float* o = out + (long)h * DIM + lane * 4;
    atomicAdd(o + 0, beta * m.x);
    atomicAdd(o + 1, beta * m.y);
    atomicAdd(o + 2, beta * m.z);
    atomicAdd(o + 3, beta * m.w);
}

// ---------------------------------------------------------------------------
extern "C" void kernel_launch(void* const* d_in, const int* in_sizes, int n_in,
                              void* d_out, int out_size)
{
    const float* emb      = (const float*)d_in[0];
    const void*  trip     = (const void*)d_in[1];
    const float* attn_w   = (const float*)d_in[2];
    const float* attn_b   = (const float*)d_in[3];
    const float* attn_bin = (const float*)d_in[4];
    const float* attn_vec = (const float*)d_in[5];
    const float* aggr_w   = (const float*)d_in[6];
    const float* aggr_b   = (const float*)d_in[7];
    float*       out      = (float*)d_out;

    int M = in_sizes[0] / DIM;        // 20000
    int E = in_sizes[1] / 3;          // 640000

    // 0. detect triplet dtype (int32 vs int64)
    detect_kernel<<<1, 128>>>((const unsigned int*)trip, E * 3);

    // 1. zero out + seg_sum
    zero_kernel<<<592, 256>>>(out, M);

    // 2. fused tables GEMM
    dim3 ggrid((M + BM - 1) / BM, (3 * DIM) / BN);
    gemm_kernel<<<ggrid, 256>>>(emb, attn_w, attn_b, aggr_w, aggr_b, M);

    // 3. per-edge attention values + segment sums
    int warps_per_block = 256 / 32;
    int nblocks = (E + warps_per_block - 1) / warps_per_block;
    edge_attn_kernel<<<nblocks, 256>>>(trip, attn_bin, attn_vec, E);

    // 4. per-edge weighted scatter
    edge_scatter_kernel<<<nblocks, 256>>>(trip, out, E);
}

// round 3
// speedup vs baseline: 1.4742x; 1.4742x over previous
#include <cuda_runtime.h>
#include <cuda_bf16.h>

// Problem constants (fixed by the dataset)
#define NUM_REL_MAX   20000
#define NUM_EDGES_MAX 640000
#define DIM           128
#define NUM_HEAD      8
#define DIM_HID       16
#define NEG_SLOPE     0.2f

// Scratch (device globals -- no allocation allowed)
__device__ float g_A[NUM_REL_MAX * DIM];       // emb @ W1^T + attn_bias
__device__ float g_B[NUM_REL_MAX * DIM];       // emb @ W2^T
__device__ float g_MSG[NUM_REL_MAX * DIM];     // emb @ aggr^T + aggr_bias
__device__ float g_attn[NUM_EDGES_MAX * NUM_HEAD];   // per-edge exp(attn_raw)
__device__ float g_segsum[NUM_REL_MAX * NUM_HEAD];   // sum then reciprocal
__device__ int   g_is64;                             // triplet dtype flag

__device__ __forceinline__ float leaky(float x) {
    return x >= 0.0f ? x : NEG_SLOPE * x;
}

// Vector global reduction (sm_90+): one instruction for 4 lanes-worth of adds.
__device__ __forceinline__ void red_add_v4(float* addr, float a, float b,
                                           float c, float d) {
    asm volatile("red.global.add.v4.f32 [%0], {%1, %2, %3, %4};"
                 :: "l"(addr), "f"(a), "f"(b), "f"(c), "f"(d)
                 : "memory");
}

// ---------------------------------------------------------------------------
// Detect triplet dtype: int64 values < 2^31 -> all odd 32-bit words are 0.
// ---------------------------------------------------------------------------
__global__ void detect_kernel(const unsigned int* __restrict__ trip_w, int nwords) {
    __shared__ int any_nonzero;
    if (threadIdx.x == 0) any_nonzero = 0;
    __syncthreads();
    int i = 1 + 2 * threadIdx.x;   // odd words
    if (i < nwords && i < 512) {
        if (trip_w[i] != 0u) atomicOr(&any_nonzero, 1);
    }
    __syncthreads();
    if (threadIdx.x == 0) g_is64 = any_nonzero ? 0 : 1;
}

// ---------------------------------------------------------------------------
// Zero init: out [M*128] and g_segsum [M*8]
// ---------------------------------------------------------------------------
__global__ void zero_kernel(float* __restrict__ out, int M) {
    int n_out = M * DIM;
    int n_seg = M * NUM_HEAD;
    int total = n_out + n_seg;
    for (int i = blockIdx.x * blockDim.x + threadIdx.x; i < total;
         i += gridDim.x * blockDim.x) {
        if (i < n_out) out[i] = 0.0f;
        else g_segsum[i - n_out] = 0.0f;
    }
}

// ---------------------------------------------------------------------------
// Fused SGEMM: P[M, 384] = emb[M,128] @ Wc[384,128]^T  (+ biases)
//   cols [0,128)   -> g_A   (attn_w[c][0:128] + attn_b[c])
//   cols [128,256) -> g_B   (attn_w[c-128][128:256])
//   cols [256,384) -> g_MSG (aggr_w[c-256] + aggr_b)
// ---------------------------------------------------------------------------
#define BM 64
#define BN 64

__global__ __launch_bounds__(256) void gemm_kernel(
    const float* __restrict__ emb,
    const float* __restrict__ attn_w,   // [128, 256]
    const float* __restrict__ attn_b,   // [128]
    const float* __restrict__ aggr_w,   // [128, 128]
    const float* __restrict__ aggr_b,   // [128]
    int M)
{
    __shared__ float As[DIM][BM];   // As[k][row]
    __shared__ float Ws[DIM][BN];   // Ws[k][col]

    int tid = threadIdx.x;
    int m0 = blockIdx.x * BM;
    int c0 = blockIdx.y * BN;

    #pragma unroll
    for (int i = 0; i < 8; i++) {
        int linear = tid + i * 256;
        int row = linear & 63;
        int c4  = linear >> 6;
        float4 v = make_float4(0.f, 0.f, 0.f, 0.f);
        int gr = m0 + row;
        if (gr < M) v = *(const float4*)(emb + (long)gr * DIM + c4 * 4);
        As[c4 * 4 + 0][row] = v.x;
        As[c4 * 4 + 1][row] = v.y;
        As[c4 * 4 + 2][row] = v.z;
        As[c4 * 4 + 3][row] = v.w;
    }
    #pragma unroll
    for (int i = 0; i < 8; i++) {
        int linear = tid + i * 256;
        int col = linear & 63;
        int c4  = linear >> 6;
        int gc = c0 + col;
        const float* wrow;
        if (gc < 128)      wrow = attn_w + (long)gc * 256;
        else if (gc < 256) wrow = attn_w + (long)(gc - 128) * 256 + 128;
        else               wrow = aggr_w + (long)(gc - 256) * 128;
        float4 v = *(const float4*)(wrow + c4 * 4);
        Ws[c4 * 4 + 0][col] = v.x;
        Ws[c4 * 4 + 1][col] = v.y;
        Ws[c4 * 4 + 2][col] = v.z;
        Ws[c4 * 4 + 3][col] = v.w;
    }
    __syncthreads();

    int ty = tid >> 4;
    int tx = tid & 15;
    float acc[4][4] = {};

    #pragma unroll 16
    for (int k = 0; k < DIM; k++) {
        float4 a = *(const float4*)&As[k][ty * 4];
        float4 w = *(const float4*)&Ws[k][tx * 4];
        float av[4] = {a.x, a.y, a.z, a.w};
        float wv[4] = {w.x, w.y, w.z, w.w};
        #pragma unroll
        for (int i = 0; i < 4; i++)
            #pragma unroll
            for (int j = 0; j < 4; j++)
                acc[i][j] += av[i] * wv[j];
    }

    #pragma unroll
    for (int i = 0; i < 4; i++) {
        int gr = m0 + ty * 4 + i;
        if (gr >= M) continue;
        #pragma unroll
        for (int j = 0; j < 4; j++) {
            int gc = c0 + tx * 4 + j;
            float val = acc[i][j];
            if (gc < 128) {
                g_A[(long)gr * DIM + gc] = val + attn_b[gc];
            } else if (gc < 256) {
                g_B[(long)gr * DIM + (gc - 128)] = val;
            } else {
                g_MSG[(long)gr * DIM + (gc - 256)] = val + aggr_b[gc - 256];
            }
        }
    }
}

// ---------------------------------------------------------------------------
// Triplet fetch handling either int32 or int64 storage.
// ---------------------------------------------------------------------------
__device__ __forceinline__ void load_triplet(const void* trip, int is64, long e,
                                             int& h, int& t, int& b) {
    if (is64) {
        const long long* p = (const long long*)trip;
        h = (int)p[e * 3 + 0];
        t = (int)p[e * 3 + 1];
        b = (int)p[e * 3 + 2];
    } else {
        const int* p = (const int*)trip;
        h = p[e * 3 + 0];
        t = p[e * 3 + 1];
        b = p[e * 3 + 2];
    }
}

// ---------------------------------------------------------------------------
// Edge pass 1: one warp per edge; exp(attn) + seg_sum atomics.
// ---------------------------------------------------------------------------
__global__ __launch_bounds__(256) void edge_attn_kernel(
    const void* __restrict__ trip,
    const float* __restrict__ attn_bin,   // [10, 8]
    const float* __restrict__ attn_vec,   // [128]
    int E)
{
    long warp = (long)(blockIdx.x * (blockDim.x >> 5)) + (threadIdx.x >> 5);
    int lane = threadIdx.x & 31;
    if (warp >= E) return;

    int is64 = g_is64;
    int h, t, b;
    load_triplet(trip, is64, warp, h, t, b);

    float4 a  = *(const float4*)(g_A + (long)h * DIM + lane * 4);
    float4 bb = *(const float4*)(g_B + (long)t * DIM + lane * 4);
    float4 v  = *(const float4*)(attn_vec + lane * 4);

    float s = leaky(a.x + bb.x) * v.x
            + leaky(a.y + bb.y) * v.y
            + leaky(a.z + bb.z) * v.z
            + leaky(a.w + bb.w) * v.w;
    s += __shfl_xor_sync(0xFFFFFFFFu, s, 1);
    s += __shfl_xor_sync(0xFFFFFFFFu, s, 2);

    if ((lane & 3) == 0) {
        int k = lane >> 2;
        float ab = __ldg(attn_bin + b * NUM_HEAD + k);
        float val = __expf(s + leaky(ab));
        g_attn[warp * NUM_HEAD + k] = val;
        atomicAdd(&g_segsum[(long)h * NUM_HEAD + k], val);
    }
}

// ---------------------------------------------------------------------------
// Reciprocal pass: g_segsum <- 1 / (g_segsum + 1e-16)
// ---------------------------------------------------------------------------
__global__ void rcp_kernel(int n) {
    int i = blockIdx.x * blockDim.x + threadIdx.x;
    if (i < n) g_segsum[i] = __frcp_rn(g_segsum[i] + 1e-16f);
}

// ---------------------------------------------------------------------------
// Edge pass 2: one warp per edge. beta = val * inv_segsum;
// out[h] += beta * MSG[t] via red.global.add.v4.f32
// ---------------------------------------------------------------------------
__global__ __launch_bounds__(256) void edge_scatter_kernel(
    const void* __restrict__ trip,
    float* __restrict__ out,
    int E)
{
    long warp = (long)(blockIdx.x * (blockDim.x >> 5)) + (threadIdx.x >> 5);
    int lane = threadIdx.x & 31;
    if (warp >= E) return;

    int is64 = g_is64;
    int h, t, b;
    load_triplet(trip, is64, warp, h, t, b);

    int k = lane >> 2;
    float val = g_attn[warp * NUM_HEAD + k];
    float inv = g_segsum[(long)h * NUM_HEAD + k];
    float beta = val * inv;

    float4 m = *(const float4*)(g_MSG + (long)t * DIM + lane * 4);
    float* o = out + (long)h * DIM + lane * 4;
    red_add_v4(o, beta * m.x, beta * m.y, beta * m.z, beta * m.w);
}

// ---------------------------------------------------------------------------
extern "C" void kernel_launch(void* const* d_in, const int* in_sizes, int n_in,
                              void* d_out, int out_size)
{
    const float* emb      = (const float*)d_in[0];
    const void*  trip     = (const void*)d_in[1];
    const float* attn_w   = (const float*)d_in[2];
    const float* attn_b   = (const float*)d_in[3];
    const float* attn_bin = (const float*)d_in[4];
    const float* attn_vec = (const float*)d_in[5];
    const float* aggr_w   = (const float*)d_in[6];
    const float* aggr_b   = (const float*)d_in[7];
    float*       out      = (float*)d_out;

    int M = in_sizes[0] / DIM;        // 20000
    int E = in_sizes[1] / 3;          // 640000

    // 0. detect triplet dtype (int32 vs int64)
    detect_kernel<<<1, 128>>>((const unsigned int*)trip, E * 3);

    // 1. zero out + seg_sum
    zero_kernel<<<592, 256>>>(out, M);

    // 2. fused tables GEMM
    dim3 ggrid((M + BM - 1) / BM, (3 * DIM) / BN);
    gemm_kernel<<<ggrid, 256>>>(emb, attn_w, attn_b, aggr_w, aggr_b, M);

    // 3. per-edge attention values + segment sums
    int warps_per_block = 256 / 32;
    int nblocks = (E + warps_per_block - 1) / warps_per_block;
    edge_attn_kernel<<<nblocks, 256>>>(trip, attn_bin, attn_vec, E);

    // 3b. reciprocal of segment sums
    int nseg = M * NUM_HEAD;
    rcp_kernel<<<(nseg + 255) / 256, 256>>>(nseg);

    // 4. per-edge weighted scatter (vector atomics)
    edge_scatter_kernel<<<nblocks, 256>>>(trip, out, E);
}

// round 5
// speedup vs baseline: 1.8929x; 1.2840x over previous
#include <cuda_runtime.h>
#include <cuda_bf16.h>

#define NUM_REL_MAX   20000
#define NUM_EDGES_MAX 640000
#define DIM           128
#define NUM_HEAD      8
#define NEG_SLOPE     0.2f

// Scratch (device globals -- no allocation allowed)
__device__ float g_A[NUM_REL_MAX * DIM];           // emb @ W1^T + attn_bias
__device__ float g_B[NUM_REL_MAX * DIM];           // emb @ W2^T
__device__ float g_MSG[NUM_REL_MAX * DIM];         // emb @ aggr^T + aggr_bias
__device__ int   g_cnt[NUM_REL_MAX];               // edges per head
__device__ int   g_off[NUM_REL_MAX + 1];           // CSR offsets
__device__ int   g_pos[NUM_REL_MAX];               // running fill positions
__device__ unsigned int g_rec[NUM_EDGES_MAX];      // packed (bin<<16)|tail
__device__ int   g_is64;                           // triplet dtype flag

__device__ __forceinline__ float leaky(float x) {
    return x >= 0.0f ? x : NEG_SLOPE * x;
}

// ---------------------------------------------------------------------------
// Triplet fetch handling either int32 or int64 storage.
// ---------------------------------------------------------------------------
__device__ __forceinline__ void load_triplet(const void* trip, int is64, long e,
                                             int& h, int& t, int& b) {
    if (is64) {
        const long long* p = (const long long*)trip;
        h = (int)p[e * 3 + 0];
        t = (int)p[e * 3 + 1];
        b = (int)p[e * 3 + 2];
    } else {
        const int* p = (const int*)trip;
        h = p[e * 3 + 0];
        t = p[e * 3 + 1];
        b = p[e * 3 + 2];
    }
}

// ---------------------------------------------------------------------------
// Detect triplet dtype + zero the histogram.
// ---------------------------------------------------------------------------
__global__ void detect_zero_kernel(const unsigned int* __restrict__ trip_w,
                                   int nwords, int M) {
    int gid = blockIdx.x * blockDim.x + threadIdx.x;
    for (int i = gid; i < M; i += gridDim.x * blockDim.x) g_cnt[i] = 0;
    if (blockIdx.x == 0) {
        __shared__ int any_nonzero;
        if (threadIdx.x == 0) any_nonzero = 0;
        __syncthreads();
        int i = 1 + 2 * threadIdx.x;   // odd 32-bit words
        if (i < nwords && i < 512) {
            if (trip_w[i] != 0u) atomicOr(&any_nonzero, 1);
        }
        __syncthreads();
        if (threadIdx.x == 0) g_is64 = any_nonzero ? 0 : 1;
    }
}

// ---------------------------------------------------------------------------
// Histogram of head indices.
// ---------------------------------------------------------------------------
__global__ __launch_bounds__(256) void hist_kernel(const void* __restrict__ trip, int E) {
    int is64 = g_is64;
    for (long e = blockIdx.x * blockDim.x + threadIdx.x; e < E;
         e += (long)gridDim.x * blockDim.x) {
        int h, t, b;
        load_triplet(trip, is64, e, h, t, b);
        atomicAdd(&g_cnt[h], 1);
    }
}

// ---------------------------------------------------------------------------
// Single-block exclusive scan of g_cnt (M <= 20480 = 512*40).
// Writes g_off (exclusive) and g_pos (copy).
// ---------------------------------------------------------------------------
#define SCAN_T 512
#define SCAN_CH 40
__global__ __launch_bounds__(SCAN_T) void scan_kernel(int M) {
    __shared__ int partial[SCAN_T];
    int tid = threadIdx.x;
    int base = tid * SCAN_CH;
    int local = 0;
    #pragma unroll
    for (int j = 0; j < SCAN_CH; j++) {
        int i = base + j;
        if (i < M) local += g_cnt[i];
    }
    partial[tid] = local;
    __syncthreads();
    // Hillis-Steele inclusive scan on partials
    for (int s = 1; s < SCAN_T; s <<= 1) {
        int v = (tid >= s) ? partial[tid - s] : 0;
        __syncthreads();
        partial[tid] += v;
        __syncthreads();
    }
    int run = (tid == 0) ? 0 : partial[tid - 1];   // exclusive base
    #pragma unroll
    for (int j = 0; j < SCAN_CH; j++) {
        int i = base + j;
        if (i < M) {
            g_off[i] = run;
            g_pos[i] = run;
            run += g_cnt[i];
        }
    }
    if (tid == SCAN_T - 1) g_off[M] = partial[SCAN_T - 1];
}

// ---------------------------------------------------------------------------
// Reorder edges into head-grouped records: rec = (bin<<16) | tail.
// ---------------------------------------------------------------------------
__global__ __launch_bounds__(256) void reorder_kernel(const void* __restrict__ trip, int E) {
    int is64 = g_is64;
    for (long e = blockIdx.x * blockDim.x + threadIdx.x; e < E;
         e += (long)gridDim.x * blockDim.x) {
        int h, t, b;
        load_triplet(trip, is64, e, h, t, b);
        int pos = atomicAdd(&g_pos[h], 1);
        g_rec[pos] = ((unsigned int)b << 16) | (unsigned int)t;
    }
}

// ---------------------------------------------------------------------------
// Fused SGEMM: P[M, 384] = emb[M,128] @ Wc[384,128]^T  (+ biases)
// ---------------------------------------------------------------------------
#define BM 64
#define BN 64

__global__ __launch_bounds__(256) void gemm_kernel(
    const float* __restrict__ emb,
    const float* __restrict__ attn_w,   // [128, 256]
    const float* __restrict__ attn_b,   // [128]
    const float* __restrict__ aggr_w,   // [128, 128]
    const float* __restrict__ aggr_b,   // [128]
    int M)
{
    __shared__ float As[DIM][BM];
    __shared__ float Ws[DIM][BN];

    int tid = threadIdx.x;
    int m0 = blockIdx.x * BM;
    int c0 = blockIdx.y * BN;

    #pragma unroll
    for (int i = 0; i < 8; i++) {
        int linear = tid + i * 256;
        int row = linear & 63;
        int c4  = linear >> 6;
        float4 v = make_float4(0.f, 0.f, 0.f, 0.f);
        int gr = m0 + row;
        if (gr < M) v = *(const float4*)(emb + (long)gr * DIM + c4 * 4);
        As[c4 * 4 + 0][row] = v.x;
        As[c4 * 4 + 1][row] = v.y;
        As[c4 * 4 + 2][row] = v.z;
        As[c4 * 4 + 3][row] = v.w;
    }
    #pragma unroll
    for (int i = 0; i < 8; i++) {
        int linear = tid + i * 256;
        int col = linear & 63;
        int c4  = linear >> 6;
        int gc = c0 + col;
        const float* wrow;
        if (gc < 128)      wrow = attn_w + (long)gc * 256;
        else if (gc < 256) wrow = attn_w + (long)(gc - 128) * 256 + 128;
        else               wrow = aggr_w + (long)(gc - 256) * 128;
        float4 v = *(const float4*)(wrow + c4 * 4);
        Ws[c4 * 4 + 0][col] = v.x;
        Ws[c4 * 4 + 1][col] = v.y;
        Ws[c4 * 4 + 2][col] = v.z;
        Ws[c4 * 4 + 3][col] = v.w;
    }
    __syncthreads();

    int ty = tid >> 4;
    int tx = tid & 15;
    float acc[4][4] = {};

    #pragma unroll 16
    for (int k = 0; k < DIM; k++) {
        float4 a = *(const float4*)&As[k][ty * 4];
        float4 w = *(const float4*)&Ws[k][tx * 4];
        float av[4] = {a.x, a.y, a.z, a.w};
        float wv[4] = {w.x, w.y, w.z, w.w};
        #pragma unroll
        for (int i = 0; i < 4; i++)
            #pragma unroll
            for (int j = 0; j < 4; j++)
                acc[i][j] += av[i] * wv[j];
    }

    #pragma unroll
    for (int i = 0; i < 4; i++) {
        int gr = m0 + ty * 4 + i;
        if (gr >= M) continue;
        #pragma unroll
        for (int j = 0; j < 4; j++) {
            int gc = c0 + tx * 4 + j;
            float val = acc[i][j];
            if (gc < 128) {
                g_A[(long)gr * DIM + gc] = val + attn_b[gc];
            } else if (gc < 256) {
                g_B[(long)gr * DIM + (gc - 128)] = val;
            } else {
                g_MSG[(long)gr * DIM + (gc - 256)] = val + aggr_b[gc - 256];
            }
        }
    }
}

// ---------------------------------------------------------------------------
// Fused per-relation aggregation: one warp per head relation.
//   acc[d]  = Σ_e val_e * MSG[t_e][d]
//   ssum    = Σ_e val_e          (per head)
//   out[h]  = acc / (ssum + 1e-16)
// val_e = exp( Σ_d leaky(A[h,d]+B[t,d])·vec[d]  + leaky(attn_bin[b,k]) )
// ---------------------------------------------------------------------------
__global__ __launch_bounds__(256) void fused_aggr_kernel(
    const float* __restrict__ attn_bin,   // [10, 8]
    const float* __restrict__ attn_vec,   // [128]
    float* __restrict__ out,
    int M)
{
    __shared__ float lbin[16 * NUM_HEAD];  // leaky(attn_bin), padded
    if (threadIdx.x < 10 * NUM_HEAD)
        lbin[threadIdx.x] = leaky(attn_bin[threadIdx.x]);
    __syncthreads();

    int warp = blockIdx.x * (blockDim.x >> 5) + (threadIdx.x >> 5);
    int lane = threadIdx.x & 31;
    if (warp >= M) return;
    int h = warp;

    int e0 = g_off[h];
    int e1 = g_off[h + 1];

    // per-lane slices (lane covers dims [lane*4, lane*4+4), head k = lane>>2)
    float4 a = *(const float4*)(g_A + (long)h * DIM + lane * 4);
    float4 v = *(const float4*)(attn_vec + lane * 4);
    int k = lane >> 2;

    float4 acc = make_float4(0.f, 0.f, 0.f, 0.f);
    float ssum = 0.f;

    for (int e = e0; e < e1; e++) {
        unsigned int rec = g_rec[e];           // broadcast load
        int t = rec & 0xFFFFu;
        int b = rec >> 16;

        const float* brow = g_B + (long)t * DIM;
        const float* mrow = g_MSG + (long)t * DIM;
        float4 bb = *(const float4*)(brow + lane * 4);
        float4 m  = *(const float4*)(mrow + lane * 4);

        float s = leaky(a.x + bb.x) * v.x
                + leaky(a.y + bb.y) * v.y
                + leaky(a.z + bb.z) * v.z
                + leaky(a.w + bb.w) * v.w;
        s += __shfl_xor_sync(0xFFFFFFFFu, s, 1);
        s += __shfl_xor_sync(0xFFFFFFFFu, s, 2);   // all 4 lanes of head k have s

        float val = __expf(s + lbin[b * NUM_HEAD + k]);

        acc.x += val * m.x;
        acc.y += val * m.y;
        acc.z += val * m.z;
        acc.w += val * m.w;
        ssum  += val;
    }

    float inv = __frcp_rn(ssum + 1e-16f);
    float4 o = make_float4(acc.x * inv, acc.y * inv, acc.z * inv, acc.w * inv);
    *(float4*)(out + (long)h * DIM + lane * 4) = o;
}

// ---------------------------------------------------------------------------
extern "C" void kernel_launch(void* const* d_in, const int* in_sizes, int n_in,
                              void* d_out, int out_size)
{
    const float* emb      = (const float*)d_in[0];
    const void*  trip     = (const void*)d_in[1];
    const float* attn_w   = (const float*)d_in[2];
    const float* attn_b   = (const float*)d_in[3];
    const float* attn_bin = (const float*)d_in[4];
    const float* attn_vec = (const float*)d_in[5];
    const float* aggr_w   = (const float*)d_in[6];
    const float* aggr_b   = (const float*)d_in[7];
    float*       out      = (float*)d_out;

    int M = in_sizes[0] / DIM;        // 20000
    int E = in_sizes[1] / 3;          // 640000

    // 0. dtype detect + histogram zero
    detect_zero_kernel<<<80, 256>>>((const unsigned int*)trip, E * 3, M);

    // 1. fused tables GEMM (independent of edge indexing)
    dim3 ggrid((M + BM - 1) / BM, (3 * DIM) / BN);
    gemm_kernel<<<ggrid, 256>>>(emb, attn_w, attn_b, aggr_w, aggr_b, M);

    // 2. counting sort by head
    hist_kernel<<<592, 256>>>(trip, E);
    scan_kernel<<<1, SCAN_T>>>(M);
    reorder_kernel<<<592, 256>>>(trip, E);

    // 3. fused per-relation attention + aggregation
    int warps_per_block = 256 / 32;
    int nblocks = (M + warps_per_block - 1) / warps_per_block;
    fused_aggr_kernel<<<nblocks, 256>>>(attn_bin, attn_vec, out, M);
}

// round 6
// speedup vs baseline: 1.9064x; 1.0071x over previous
#include <cuda_runtime.h>
#include <cuda_bf16.h>

#define NUM_REL_MAX   20000
#define NUM_EDGES_MAX 640000
#define DIM           128
#define NUM_HEAD      8
#define NEG_SLOPE     0.2f

// Scratch (device globals -- no allocation allowed)
__device__ float g_A[NUM_REL_MAX * DIM];           // emb @ W1^T + attn_bias
__device__ float g_B[NUM_REL_MAX * DIM];           // emb @ W2^T
__device__ float g_MSG[NUM_REL_MAX * DIM];         // emb @ aggr^T + aggr_bias
__device__ int   g_cnt[NUM_REL_MAX];               // edges per head
__device__ int   g_off[NUM_REL_MAX + 1];           // CSR offsets
__device__ int   g_pos[NUM_REL_MAX];               // running fill positions
__device__ unsigned int g_rec[NUM_EDGES_MAX];      // packed (bin<<16)|tail
__device__ int   g_is64;                           // triplet dtype flag

__device__ __forceinline__ float leaky(float x) {
    return x >= 0.0f ? x : NEG_SLOPE * x;
}

// ---------------------------------------------------------------------------
// Triplet fetch handling either int32 or int64 storage.
// ---------------------------------------------------------------------------
__device__ __forceinline__ void load_triplet(const void* trip, int is64, long e,
                                             int& h, int& t, int& b) {
    if (is64) {
        const long long* p = (const long long*)trip;
        h = (int)p[e * 3 + 0];
        t = (int)p[e * 3 + 1];
        b = (int)p[e * 3 + 2];
    } else {
        const int* p = (const int*)trip;
        h = p[e * 3 + 0];
        t = p[e * 3 + 1];
        b = p[e * 3 + 2];
    }
}

// ---------------------------------------------------------------------------
// Detect triplet dtype + zero the histogram.
// ---------------------------------------------------------------------------
__global__ void detect_zero_kernel(const unsigned int* __restrict__ trip_w,
                                   int nwords, int M) {
    int gid = blockIdx.x * blockDim.x + threadIdx.x;
    for (int i = gid; i < M; i += gridDim.x * blockDim.x) g_cnt[i] = 0;
    if (blockIdx.x == 0) {
        __shared__ int any_nonzero;
        if (threadIdx.x == 0) any_nonzero = 0;
        __syncthreads();
        int i = 1 + 2 * threadIdx.x;   // odd 32-bit words
        if (i < nwords && i < 512) {
            if (trip_w[i] != 0u) atomicOr(&any_nonzero, 1);
        }
        __syncthreads();
        if (threadIdx.x == 0) g_is64 = any_nonzero ? 0 : 1;
    }
}

// ---------------------------------------------------------------------------
// Histogram of head indices.
// ---------------------------------------------------------------------------
__global__ __launch_bounds__(256) void hist_kernel(const void* __restrict__ trip, int E) {
    int is64 = g_is64;
    for (long e = blockIdx.x * blockDim.x + threadIdx.x; e < E;
         e += (long)gridDim.x * blockDim.x) {
        int h, t, b;
        load_triplet(trip, is64, e, h, t, b);
        atomicAdd(&g_cnt[h], 1);
    }
}

// ---------------------------------------------------------------------------
// Single-block exclusive scan of g_cnt (M <= 20480 = 512*40).
// Counts cached in a per-thread local array: loads are issued once,
// independently (high MLP), instead of twice with a serial dependency.
// ---------------------------------------------------------------------------
#define SCAN_T 512
#define SCAN_CH 40
__global__ __launch_bounds__(SCAN_T) void scan_kernel(int M) {
    __shared__ int partial[SCAN_T];
    int tid = threadIdx.x;
    int base = tid * SCAN_CH;

    int c[SCAN_CH];
    #pragma unroll
    for (int j = 0; j < SCAN_CH; j++) {
        int i = base + j;
        c[j] = (i < M) ? g_cnt[i] : 0;
    }
    int local = 0;
    #pragma unroll
    for (int j = 0; j < SCAN_CH; j++) local += c[j];

    partial[tid] = local;
    __syncthreads();
    // Hillis-Steele inclusive scan on partials
    for (int s = 1; s < SCAN_T; s <<= 1) {
        int v = (tid >= s) ? partial[tid - s] : 0;
        __syncthreads();
        partial[tid] += v;
        __syncthreads();
    }
    int run = (tid == 0) ? 0 : partial[tid - 1];   // exclusive base
    #pragma unroll
    for (int j = 0; j < SCAN_CH; j++) {
        int i = base + j;
        if (i < M) {
            g_off[i] = run;
            g_pos[i] = run;
            run += c[j];
        }
    }
    if (tid == SCAN_T - 1) g_off[M] = partial[SCAN_T - 1];
}

// ---------------------------------------------------------------------------
// Reorder edges into head-grouped records: rec = (bin<<16) | tail.
// ---------------------------------------------------------------------------
__global__ __launch_bounds__(256) void reorder_kernel(const void* __restrict__ trip, int E) {
    int is64 = g_is64;
    for (long e = blockIdx.x * blockDim.x + threadIdx.x; e < E;
         e += (long)gridDim.x * blockDim.x) {
        int h, t, b;
        load_triplet(trip, is64, e, h, t, b);
        int pos = atomicAdd(&g_pos[h], 1);
        g_rec[pos] = ((unsigned int)b << 16) | (unsigned int)t;
    }
}

// ---------------------------------------------------------------------------
// Fused SGEMM: P[M, 384] = emb[M,128] @ Wc[384,128]^T  (+ biases)
// ---------------------------------------------------------------------------
#define BM 64
#define BN 64

__global__ __launch_bounds__(256) void gemm_kernel(
    const float* __restrict__ emb,
    const float* __restrict__ attn_w,   // [128, 256]
    const float* __restrict__ attn_b,   // [128]
    const float* __restrict__ aggr_w,   // [128, 128]
    const float* __restrict__ aggr_b,   // [128]
    int M)
{
    __shared__ float As[DIM][BM];
    __shared__ float Ws[DIM][BN];

    int tid = threadIdx.x;
    int m0 = blockIdx.x * BM;
    int c0 = blockIdx.y * BN;

    #pragma unroll
    for (int i = 0; i < 8; i++) {
        int linear = tid + i * 256;
        int row = linear & 63;
        int c4  = linear >> 6;
        float4 v = make_float4(0.f, 0.f, 0.f, 0.f);
        int gr = m0 + row;
        if (gr < M) v = *(const float4*)(emb + (long)gr * DIM + c4 * 4);
        As[c4 * 4 + 0][row] = v.x;
        As[c4 * 4 + 1][row] = v.y;
        As[c4 * 4 + 2][row] = v.z;
        As[c4 * 4 + 3][row] = v.w;
    }
    #pragma unroll
    for (int i = 0; i < 8; i++) {
        int linear = tid + i * 256;
        int col = linear & 63;
        int c4  = linear >> 6;
        int gc = c0 + col;
        const float* wrow;
        if (gc < 128)      wrow = attn_w + (long)gc * 256;
        else if (gc < 256) wrow = attn_w + (long)(gc - 128) * 256 + 128;
        else               wrow = aggr_w + (long)(gc - 256) * 128;
        float4 v = *(const float4*)(wrow + c4 * 4);
        Ws[c4 * 4 + 0][col] = v.x;
        Ws[c4 * 4 + 1][col] = v.y;
        Ws[c4 * 4 + 2][col] = v.z;
        Ws[c4 * 4 + 3][col] = v.w;
    }
    __syncthreads();

    int ty = tid >> 4;
    int tx = tid & 15;
    float acc[4][4] = {};

    #pragma unroll 16
    for (int k = 0; k < DIM; k++) {
        float4 a = *(const float4*)&As[k][ty * 4];
        float4 w = *(const float4*)&Ws[k][tx * 4];
        float av[4] = {a.x, a.y, a.z, a.w};
        float wv[4] = {w.x, w.y, w.z, w.w};
        #pragma unroll
        for (int i = 0; i < 4; i++)
            #pragma unroll
            for (int j = 0; j < 4; j++)
                acc[i][j] += av[i] * wv[j];
    }

    #pragma unroll
    for (int i = 0; i < 4; i++) {
        int gr = m0 + ty * 4 + i;
        if (gr >= M) continue;
        #pragma unroll
        for (int j = 0; j < 4; j++) {
            int gc = c0 + tx * 4 + j;
            float val = acc[i][j];
            if (gc < 128) {
                g_A[(long)gr * DIM + gc] = val + attn_b[gc];
            } else if (gc < 256) {
                g_B[(long)gr * DIM + (gc - 128)] = val;
            } else {
                g_MSG[(long)gr * DIM + (gc - 256)] = val + aggr_b[gc - 256];
            }
        }
    }
}

// ---------------------------------------------------------------------------
// Fused per-relation aggregation: one warp per head relation.
// ---------------------------------------------------------------------------
__global__ __launch_bounds__(256) void fused_aggr_kernel(
    const float* __restrict__ attn_bin,   // [10, 8]
    const float* __restrict__ attn_vec,   // [128]
    float* __restrict__ out,
    int M)
{
    __shared__ float lbin[16 * NUM_HEAD];
    if (threadIdx.x < 10 * NUM_HEAD)
        lbin[threadIdx.x] = leaky(attn_bin[threadIdx.x]);
    __syncthreads();

    int warp = blockIdx.x * (blockDim.x >> 5) + (threadIdx.x >> 5);
    int lane = threadIdx.x & 31;
    if (warp >= M) return;
    int h = warp;

    int e0 = g_off[h];
    int e1 = g_off[h + 1];

    float4 a = *(const float4*)(g_A + (long)h * DIM + lane * 4);
    float4 v = *(const float4*)(attn_vec + lane * 4);
    int k = lane >> 2;

    float4 acc = make_float4(0.f, 0.f, 0.f, 0.f);
    float ssum = 0.f;

    for (int e = e0; e < e1; e++) {
        unsigned int rec = g_rec[e];           // broadcast load
        int t = rec & 0xFFFFu;
        int b = rec >> 16;

        const float* brow = g_B + (long)t * DIM;
        const float* mrow = g_MSG + (long)t * DIM;
        float4 bb = *(const float4*)(brow + lane * 4);
        float4 m  = *(const float4*)(mrow + lane * 4);

        float s = leaky(a.x + bb.x) * v.x
                + leaky(a.y + bb.y) * v.y
                + leaky(a.z + bb.z) * v.z
                + leaky(a.w + bb.w) * v.w;
        s += __shfl_xor_sync(0xFFFFFFFFu, s, 1);
        s += __shfl_xor_sync(0xFFFFFFFFu, s, 2);

        float val = __expf(s + lbin[b * NUM_HEAD + k]);

        acc.x += val * m.x;
        acc.y += val * m.y;
        acc.z += val * m.z;
        acc.w += val * m.w;
        ssum  += val;
    }

    float inv = __frcp_rn(ssum + 1e-16f);
    float4 o = make_float4(acc.x * inv, acc.y * inv, acc.z * inv, acc.w * inv);
    *(float4*)(out + (long)h * DIM + lane * 4) = o;
}

// ---------------------------------------------------------------------------
extern "C" void kernel_launch(void* const* d_in, const int* in_sizes, int n_in,
                              void* d_out, int out_size)
{
    const float* emb      = (const float*)d_in[0];
    const void*  trip     = (const void*)d_in[1];
    const float* attn_w   = (const float*)d_in[2];
    const float* attn_b   = (const float*)d_in[3];
    const float* attn_bin = (const float*)d_in[4];
    const float* attn_vec = (const float*)d_in[5];
    const float* aggr_w   = (const float*)d_in[6];
    const float* aggr_b   = (const float*)d_in[7];
    float*       out      = (float*)d_out;

    int M = in_sizes[0] / DIM;        // 20000
    int E = in_sizes[1] / 3;          // 640000

    // One-time host-side stream/event setup (host objects, no device memory).
    static cudaStream_t s_gemm = nullptr;
    static cudaEvent_t ev_fork = nullptr, ev_join = nullptr;
    if (s_gemm == nullptr) {
        cudaStreamCreateWithFlags(&s_gemm, cudaStreamNonBlocking);
        cudaEventCreateWithFlags(&ev_fork, cudaEventDisableTiming);
        cudaEventCreateWithFlags(&ev_join, cudaEventDisableTiming);
    }

    // Fork: GEMM (independent of edge indexing) runs on the side stream.
    cudaEventRecord(ev_fork, 0);
    cudaStreamWaitEvent(s_gemm, ev_fork, 0);

    dim3 ggrid((M + BM - 1) / BM, (3 * DIM) / BN);
    gemm_kernel<<<ggrid, 256, 0, s_gemm>>>(emb, attn_w, attn_b, aggr_w, aggr_b, M);
    cudaEventRecord(ev_join, s_gemm);

    // Main stream: counting sort by head.
    detect_zero_kernel<<<80, 256>>>((const unsigned int*)trip, E * 3, M);
    hist_kernel<<<592, 256>>>(trip, E);
    scan_kernel<<<1, SCAN_T>>>(M);
    reorder_kernel<<<592, 256>>>(trip, E);

    // Join: fused aggregation needs both the tables and the sorted edges.
    cudaStreamWaitEvent(0, ev_join, 0);

    int warps_per_block = 256 / 32;
    int nblocks = (M + warps_per_block - 1) / warps_per_block;
    fused_aggr_kernel<<<nblocks, 256>>>(attn_bin, attn_vec, out, M);
}

// round 7
// speedup vs baseline: 2.1796x; 1.1433x over previous
#include <cuda_runtime.h>
#include <cuda_bf16.h>

#define NUM_REL_MAX   20000
#define NUM_EDGES_MAX 640000
#define DIM           128
#define NUM_HEAD      8
#define NEG_SLOPE     0.2f
#define SCAN_B        256
#define MAX_BLKS      ((NUM_REL_MAX + SCAN_B - 1) / SCAN_B)   // 79

// Scratch (device globals -- no allocation allowed)
__device__ float g_A[NUM_REL_MAX * DIM];           // emb @ W1^T + attn_bias
__device__ float g_B[NUM_REL_MAX * DIM];           // emb @ W2^T
__device__ float g_MSG[NUM_REL_MAX * DIM];         // emb @ aggr^T + aggr_bias
__device__ int   g_cnt[NUM_REL_MAX];               // edges per head
__device__ int   g_off[NUM_REL_MAX + 1];           // CSR offsets
__device__ int   g_pos[NUM_REL_MAX];               // running fill positions
__device__ int   g_blk[MAX_BLKS + 1];              // per-block sums / offsets
__device__ unsigned int g_rec[NUM_EDGES_MAX];      // packed (bin<<16)|tail
__device__ int   g_is64;                           // triplet dtype flag

__device__ __forceinline__ float leaky(float x) {
    return x >= 0.0f ? x : NEG_SLOPE * x;
}

// ---------------------------------------------------------------------------
// Triplet fetch handling either int32 or int64 storage.
// ---------------------------------------------------------------------------
__device__ __forceinline__ void load_triplet(const void* trip, int is64, long e,
                                             int& h, int& t, int& b) {
    if (is64) {
        const long long* p = (const long long*)trip;
        h = (int)p[e * 3 + 0];
        t = (int)p[e * 3 + 1];
        b = (int)p[e * 3 + 2];
    } else {
        const int* p = (const int*)trip;
        h = p[e * 3 + 0];
        t = p[e * 3 + 1];
        b = p[e * 3 + 2];
    }
}

// ---------------------------------------------------------------------------
// Detect triplet dtype + zero the histogram.
// ---------------------------------------------------------------------------
__global__ void detect_zero_kernel(const unsigned int* __restrict__ trip_w,
                                   int nwords, int M) {
    int gid = blockIdx.x * blockDim.x + threadIdx.x;
    for (int i = gid; i < M; i += gridDim.x * blockDim.x) g_cnt[i] = 0;
    if (blockIdx.x == 0) {
        __shared__ int any_nonzero;
        if (threadIdx.x == 0) any_nonzero = 0;
        __syncthreads();
        int i = 1 + 2 * threadIdx.x;   // odd 32-bit words
        if (i < nwords && i < 512) {
            if (trip_w[i] != 0u) atomicOr(&any_nonzero, 1);
        }
        __syncthreads();
        if (threadIdx.x == 0) g_is64 = any_nonzero ? 0 : 1;
    }
}

// ---------------------------------------------------------------------------
// Histogram of head indices.
// ---------------------------------------------------------------------------
__global__ __launch_bounds__(256) void hist_kernel(const void* __restrict__ trip, int E) {
    int is64 = g_is64;
    for (long e = blockIdx.x * blockDim.x + threadIdx.x; e < E;
         e += (long)gridDim.x * blockDim.x) {
        int h, t, b;
        load_triplet(trip, is64, e, h, t, b);
        atomicAdd(&g_cnt[h], 1);
    }
}

// ---------------------------------------------------------------------------
// Hierarchical scan, stage 1: per-block (256-elem) exclusive scan.
// Writes local exclusive prefix to g_off[i], block total to g_blk[blk].
// ---------------------------------------------------------------------------
__global__ __launch_bounds__(SCAN_B) void scan1_kernel(int M) {
    __shared__ int wsum[SCAN_B / 32];
    int tid = threadIdx.x;
    int lane = tid & 31;
    int wid = tid >> 5;
    int i = blockIdx.x * SCAN_B + tid;
    int v = (i < M) ? g_cnt[i] : 0;

    // inclusive warp scan
    int x = v;
    #pragma unroll
    for (int s = 1; s < 32; s <<= 1) {
        int y = __shfl_up_sync(0xFFFFFFFFu, x, s);
        if (lane >= s) x += y;
    }
    if (lane == 31) wsum[wid] = x;
    __syncthreads();
    if (wid == 0) {
        int w = (lane < SCAN_B / 32) ? wsum[lane] : 0;
        #pragma unroll
        for (int s = 1; s < SCAN_B / 32; s <<= 1) {
            int y = __shfl_up_sync(0xFFFFFFFFu, w, s);
            if (lane >= s) w += y;
        }
        if (lane < SCAN_B / 32) wsum[lane] = w;
    }
    __syncthreads();
    int excl = x - v + (wid > 0 ? wsum[wid - 1] : 0);
    if (i < M) g_off[i] = excl;
    if (tid == SCAN_B - 1) g_blk[blockIdx.x] = excl + v;
}

// ---------------------------------------------------------------------------
// Stage 2: one warp scans the block sums (nblk <= 96) -> exclusive offsets.
// ---------------------------------------------------------------------------
__global__ void scan2_kernel(int nblk, int M) {
    int lane = threadIdx.x;   // 32 threads
    int vals[3];
    int total = 0;
    // serial-across-chunks exclusive scan, 3 chunks of 32
    #pragma unroll
    for (int ch = 0; ch < 3; ch++) {
        int i = ch * 32 + lane;
        int v = (i < nblk) ? g_blk[i] : 0;
        int x = v;
        #pragma unroll
        for (int s = 1; s < 32; s <<= 1) {
            int y = __shfl_up_sync(0xFFFFFFFFu, x, s);
            if (lane >= s) x += y;
        }
        vals[ch] = x - v + total;                 // exclusive + running base
        total += __shfl_sync(0xFFFFFFFFu, x, 31); // chunk total
    }
    #pragma unroll
    for (int ch = 0; ch < 3; ch++) {
        int i = ch * 32 + lane;
        if (i < nblk) g_blk[i] = vals[ch];
    }
    if (lane == 0) g_off[M] = total;   // grand total = E
}

// ---------------------------------------------------------------------------
// Stage 3: add block offsets; copy to g_pos.
// ---------------------------------------------------------------------------
__global__ __launch_bounds__(SCAN_B) void scan3_kernel(int M) {
    int i = blockIdx.x * SCAN_B + threadIdx.x;
    if (i < M) {
        int o = g_off[i] + g_blk[blockIdx.x];
        g_off[i] = o;
        g_pos[i] = o;
    }
}

// ---------------------------------------------------------------------------
// Reorder edges into head-grouped records: rec = (bin<<16) | tail.
// ---------------------------------------------------------------------------
__global__ __launch_bounds__(256) void reorder_kernel(const void* __restrict__ trip, int E) {
    int is64 = g_is64;
    for (long e = blockIdx.x * blockDim.x + threadIdx.x; e < E;
         e += (long)gridDim.x * blockDim.x) {
        int h, t, b;
        load_triplet(trip, is64, e, h, t, b);
        int pos = atomicAdd(&g_pos[h], 1);
        g_rec[pos] = ((unsigned int)b << 16) | (unsigned int)t;
    }
}

// ---------------------------------------------------------------------------
// Fused SGEMM: P[M, 384] = emb[M,128] @ Wc[384,128]^T  (+ biases)
// ---------------------------------------------------------------------------
#define BM 64
#define BN 64

__global__ __launch_bounds__(256) void gemm_kernel(
    const float* __restrict__ emb,
    const float* __restrict__ attn_w,   // [128, 256]
    const float* __restrict__ attn_b,   // [128]
    const float* __restrict__ aggr_w,   // [128, 128]
    const float* __restrict__ aggr_b,   // [128]
    int M)
{
    __shared__ float As[DIM][BM];
    __shared__ float Ws[DIM][BN];

    int tid = threadIdx.x;
    int m0 = blockIdx.x * BM;
    int c0 = blockIdx.y * BN;

    #pragma unroll
    for (int i = 0; i < 8; i++) {
        int linear = tid + i * 256;
        int row = linear & 63;
        int c4  = linear >> 6;
        float4 v = make_float4(0.f, 0.f, 0.f, 0.f);
        int gr = m0 + row;
        if (gr < M) v = *(const float4*)(emb + (long)gr * DIM + c4 * 4);
        As[c4 * 4 + 0][row] = v.x;
        As[c4 * 4 + 1][row] = v.y;
        As[c4 * 4 + 2][row] = v.z;
        As[c4 * 4 + 3][row] = v.w;
    }
    #pragma unroll
    for (int i = 0; i < 8; i++) {
        int linear = tid + i * 256;
        int col = linear & 63;
        int c4  = linear >> 6;
        int gc = c0 + col;
        const float* wrow;
        if (gc < 128)      wrow = attn_w + (long)gc * 256;
        else if (gc < 256) wrow = attn_w + (long)(gc - 128) * 256 + 128;
        else               wrow = aggr_w + (long)(gc - 256) * 128;
        float4 v = *(const float4*)(wrow + c4 * 4);
        Ws[c4 * 4 + 0][col] = v.x;
        Ws[c4 * 4 + 1][col] = v.y;
        Ws[c4 * 4 + 2][col] = v.z;
        Ws[c4 * 4 + 3][col] = v.w;
    }
    __syncthreads();

    int ty = tid >> 4;
    int tx = tid & 15;
    float acc[4][4] = {};

    #pragma unroll 16
    for (int k = 0; k < DIM; k++) {
        float4 a = *(const float4*)&As[k][ty * 4];
        float4 w = *(const float4*)&Ws[k][tx * 4];
        float av[4] = {a.x, a.y, a.z, a.w};
        float wv[4] = {w.x, w.y, w.z, w.w};
        #pragma unroll
        for (int i = 0; i < 4; i++)
            #pragma unroll
            for (int j = 0; j < 4; j++)
                acc[i][j] += av[i] * wv[j];
    }

    #pragma unroll
    for (int i = 0; i < 4; i++) {
        int gr = m0 + ty * 4 + i;
        if (gr >= M) continue;
        #pragma unroll
        for (int j = 0; j < 4; j++) {
            int gc = c0 + tx * 4 + j;
            float val = acc[i][j];
            if (gc < 128) {
                g_A[(long)gr * DIM + gc] = val + attn_b[gc];
            } else if (gc < 256) {
                g_B[(long)gr * DIM + (gc - 128)] = val;
            } else {
                g_MSG[(long)gr * DIM + (gc - 256)] = val + aggr_b[gc - 256];
            }
        }
    }
}

// ---------------------------------------------------------------------------
// Fused per-relation aggregation: one warp per head relation.
// Software-pipelined: next rec is prefetched while current edge is processed.
// ---------------------------------------------------------------------------
__global__ __launch_bounds__(256) void fused_aggr_kernel(
    const float* __restrict__ attn_bin,   // [10, 8]
    const float* __restrict__ attn_vec,   // [128]
    float* __restrict__ out,
    int M)
{
    __shared__ float lbin[16 * NUM_HEAD];
    if (threadIdx.x < 10 * NUM_HEAD)
        lbin[threadIdx.x] = leaky(attn_bin[threadIdx.x]);
    __syncthreads();

    int warp = blockIdx.x * (blockDim.x >> 5) + (threadIdx.x >> 5);
    int lane = threadIdx.x & 31;
    if (warp >= M) return;
    int h = warp;

    int e0 = g_off[h];
    int e1 = g_off[h + 1];

    float4 a = *(const float4*)(g_A + (long)h * DIM + lane * 4);
    float4 v = *(const float4*)(attn_vec + lane * 4);
    int k = lane >> 2;

    float4 acc = make_float4(0.f, 0.f, 0.f, 0.f);
    float ssum = 0.f;

    if (e0 < e1) {
        unsigned int rec = __ldg(g_rec + e0);
        for (int e = e0; e < e1; e++) {
            int t = rec & 0xFFFFu;
            int b = rec >> 16;
            if (e + 1 < e1) rec = __ldg(g_rec + e + 1);   // prefetch next

            float4 bb = *(const float4*)(g_B + (long)t * DIM + lane * 4);
            float4 m  = *(const float4*)(g_MSG + (long)t * DIM + lane * 4);

            float s = leaky(a.x + bb.x) * v.x
                    + leaky(a.y + bb.y) * v.y
                    + leaky(a.z + bb.z) * v.z
                    + leaky(a.w + bb.w) * v.w;
            s += __shfl_xor_sync(0xFFFFFFFFu, s, 1);
            s += __shfl_xor_sync(0xFFFFFFFFu, s, 2);

            float val = __expf(s + lbin[b * NUM_HEAD + k]);

            acc.x += val * m.x;
            acc.y += val * m.y;
            acc.z += val * m.z;
            acc.w += val * m.w;
            ssum  += val;
        }
    }

    float inv = __frcp_rn(ssum + 1e-16f);
    float4 o = make_float4(acc.x * inv, acc.y * inv, acc.z * inv, acc.w * inv);
    *(float4*)(out + (long)h * DIM + lane * 4) = o;
}

// ---------------------------------------------------------------------------
extern "C" void kernel_launch(void* const* d_in, const int* in_sizes, int n_in,
                              void* d_out, int out_size)
{
    const float* emb      = (const float*)d_in[0];
    const void*  trip     = (const void*)d_in[1];
    const float* attn_w   = (const float*)d_in[2];
    const float* attn_b   = (const float*)d_in[3];
    const float* attn_bin = (const float*)d_in[4];
    const float* attn_vec = (const float*)d_in[5];
    const float* aggr_w   = (const float*)d_in[6];
    const float* aggr_b   = (const float*)d_in[7];
    float*       out      = (float*)d_out;

    int M = in_sizes[0] / DIM;        // 20000
    int E = in_sizes[1] / 3;          // 640000
    int nblk = (M + SCAN_B - 1) / SCAN_B;

    // One-time host-side stream/event setup (host objects, no device memory).
    static cudaStream_t s_gemm = nullptr;
    static cudaEvent_t ev_fork = nullptr, ev_join = nullptr;
    if (s_gemm == nullptr) {
        cudaStreamCreateWithFlags(&s_gemm, cudaStreamNonBlocking);
        cudaEventCreateWithFlags(&ev_fork, cudaEventDisableTiming);
        cudaEventCreateWithFlags(&ev_join, cudaEventDisableTiming);
    }

    // Fork: GEMM (independent of edge indexing) runs on the side stream.
    cudaEventRecord(ev_fork, 0);
    cudaStreamWaitEvent(s_gemm, ev_fork, 0);

    dim3 ggrid((M + BM - 1) / BM, (3 * DIM) / BN);
    gemm_kernel<<<ggrid, 256, 0, s_gemm>>>(emb, attn_w, attn_b, aggr_w, aggr_b, M);
    cudaEventRecord(ev_join, s_gemm);

    // Main stream: counting sort by head.
    detect_zero_kernel<<<80, 256>>>((const unsigned int*)trip, E * 3, M);
    hist_kernel<<<592, 256>>>(trip, E);
    scan1_kernel<<<nblk, SCAN_B>>>(M);
    scan2_kernel<<<1, 32>>>(nblk, M);
    scan3_kernel<<<nblk, SCAN_B>>>(M);
    reorder_kernel<<<592, 256>>>(trip, E);

    // Join: fused aggregation needs both the tables and the sorted edges.
    cudaStreamWaitEvent(0, ev_join, 0);

    int warps_per_block = 256 / 32;
    int nblocks = (M + warps_per_block - 1) / warps_per_block;
    fused_aggr_kernel<<<nblocks, 256>>>(attn_bin, attn_vec, out, M);
}